// round 14
// baseline (speedup 1.0000x reference)
#include <cuda_runtime.h>
#include <cuda_fp16.h>
#include <cstdint>

#define NUM_DST   10000
#define NUM_EDGES 600000
#define DN   100
#define DE   172
#define DTF  100
#define DOUT 128
#define KDIM (DN + DE + DTF)   // 372
#define NPC  6                 // k-pair chunks: k = it*64 + lane*2
#define KP1  (KDIM * 2)        // 744: phase-1 interleaved K
#define KO   (DOUT + DN)       // 228: phase-2 K

// ---------------- scratch ----------------------------------------------------
__device__ float   g_qnodes[NUM_DST * DOUT];
__device__ float   g_qbk[NUM_DST * 2];
__device__ __half2 g_Pqh[(size_t)NUM_DST * KDIM];   // [d][k] -> (head0, head1) fp16
__device__ float2  g_U[(size_t)NUM_DST * KDIM];     // [d][k] -> (head0, head1) fp32
__device__ float   g_z[NUM_DST * 2];
__device__ float   g_qbias[DOUT];
__device__ float   g_absum[2];

#define U_FLOAT4 ((NUM_DST * KDIM * 2) / 4)   // 1,860,000
#define Z_FLOAT4 ((NUM_DST * 2) / 4)          // 5,000

// outmma smem layout (bytes)
#define SM_AGG  (128 * 132 * 4)               // 67584
#define SM_AS   (128 * 68 * 4)                // 34816
#define SM_BS   (64 * 136 * 4)                // 34816
#define SM_RZ   (128 * 2 * 4)                 // 1024
#define OUT_SMEM (SM_AGG + SM_AS + SM_BS + SM_RZ)   // 138240

__device__ __forceinline__ uint32_t to_tf32(float f) {
    uint32_t r;
    asm("cvt.rna.tf32.f32 %0, %1;" : "=r"(r) : "f"(f));
    return r;
}

// ---------------- kernel 0: init (vectorized zero) + derived constants -------
__global__ void init_kernel(const float* __restrict__ time_b,
                            const float* __restrict__ wq,
                            const float* __restrict__ bq,
                            const float* __restrict__ att_bias)
{
    int idx = blockIdx.x * blockDim.x + threadIdx.x;
    float4 zero4 = make_float4(0.f, 0.f, 0.f, 0.f);
    if (idx < U_FLOAT4) ((float4*)g_U)[idx] = zero4;
    if (idx < Z_FLOAT4) ((float4*)g_z)[idx] = zero4;
    if (idx < DOUT) {
        float acc = bq[idx];
        #pragma unroll 4
        for (int t = 0; t < DTF; t++)
            acc += cosf(time_b[t]) * wq[(DN + t) * DOUT + idx];
        g_qbias[idx] = acc;
    }
    if (idx < 2) {
        float s = 0.f;
        for (int j = 0; j < DOUT / 2; j++) s += att_bias[idx * (DOUT / 2) + j];
        g_absum[idx] = s;
    }
}

// ---------------- kernel 1: Q per dst node (8 dst / block) + Q.bk ------------
__global__ __launch_bounds__(128) void qnode_kernel(const float* __restrict__ h,
                                                    const float* __restrict__ wq,
                                                    const float* __restrict__ bk)
{
    int dbase = blockIdx.x * 8;
    int c = threadIdx.x;
    __shared__ float sh[8][DN];
    __shared__ float part[8][4];
    for (int i = c; i < 8 * DN; i += 128) {
        int dl = i / DN, k = i - dl * DN;
        sh[dl][k] = h[(size_t)(dbase + dl) * DN + k];
    }
    __syncthreads();
    float qb = g_qbias[c];
    float a[8];
    #pragma unroll
    for (int d = 0; d < 8; d++) a[d] = qb;
    #pragma unroll 4
    for (int k = 0; k < DN; k++) {
        float w = wq[k * DOUT + c];
        #pragma unroll
        for (int d = 0; d < 8; d++) a[d] = fmaf(sh[d][k], w, a[d]);
    }
    #pragma unroll
    for (int d = 0; d < 8; d++)
        g_qnodes[(dbase + d) * DOUT + c] = a[d];

    float bkc = bk[c];
    float p[8];
    #pragma unroll
    for (int d = 0; d < 8; d++) p[d] = a[d] * bkc;
    #pragma unroll
    for (int off = 16; off > 0; off >>= 1)
        #pragma unroll
        for (int d = 0; d < 8; d++)
            p[d] += __shfl_xor_sync(0xffffffffu, p[d], off);
    int warp = c >> 5;
    if ((c & 31) == 0)
        #pragma unroll
        for (int d = 0; d < 8; d++) part[d][warp] = p[d];
    __syncthreads();
    if (c < 16) {
        int d = c >> 1, hh = c & 1;
        g_qbk[(dbase + d) * 2 + hh] = part[d][hh * 2] + part[d][hh * 2 + 1];
    }
}

// ---------------- kernel 1b: Pq via tf32 MMA (UNCHANGED R13) -----------------
__global__ __launch_bounds__(256) void pqmma_kernel(const float* __restrict__ wk)
{
    __shared__ float As[128][68];
    __shared__ float Bs[64][136];
    const int dbase = blockIdx.x * 128;
    const int kbase = blockIdx.y * 128;
    const int hh    = blockIdx.z;
    const int tid  = threadIdx.x;
    const int lane = tid & 31;
    const int wid  = tid >> 5;
    const int wm   = wid & 3;
    const int wn   = wid >> 2;

    for (int i = tid; i < 128 * 64; i += 256) {
        int r = i >> 6, c = i & 63;
        int d = dbase + r;
        float qv = (d < NUM_DST) ? g_qnodes[d * DOUT + hh * 64 + c] : 0.f;
        As[r][c] = __uint_as_float(to_tf32(qv));
    }
    for (int i = tid; i < 128 * 64; i += 256) {
        int n = i >> 6, c = i & 63;
        int k = kbase + n;
        float wv_ = (k < KDIM) ? wk[k * DOUT + hh * 64 + c] : 0.f;
        Bs[c][n] = __uint_as_float(to_tf32(wv_));
    }
    __syncthreads();

    float acc[2][8][4];
    #pragma unroll
    for (int mf = 0; mf < 2; mf++)
        #pragma unroll
        for (int nf = 0; nf < 8; nf++)
            #pragma unroll
            for (int r = 0; r < 4; r++) acc[mf][nf][r] = 0.f;

    #pragma unroll
    for (int ks = 0; ks < 8; ks++) {
        int acol = (lane & 3) + ks * 8;
        uint32_t a[2][4];
        #pragma unroll
        for (int mf = 0; mf < 2; mf++) {
            int rb = wm * 32 + mf * 16 + (lane >> 2);
            a[mf][0] = __float_as_uint(As[rb][acol]);
            a[mf][1] = __float_as_uint(As[rb + 8][acol]);
            a[mf][2] = __float_as_uint(As[rb][acol + 4]);
            a[mf][3] = __float_as_uint(As[rb + 8][acol + 4]);
        }
        int brow = (lane & 3) + ks * 8;
        #pragma unroll
        for (int nf = 0; nf < 8; nf++) {
            int bn = wn * 64 + nf * 8 + (lane >> 2);
            uint32_t b0 = __float_as_uint(Bs[brow][bn]);
            uint32_t b1 = __float_as_uint(Bs[brow + 4][bn]);
            #pragma unroll
            for (int mf = 0; mf < 2; mf++) {
                asm volatile(
                    "mma.sync.aligned.m16n8k8.row.col.f32.tf32.tf32.f32 "
                    "{%0,%1,%2,%3}, {%4,%5,%6,%7}, {%8,%9}, {%0,%1,%2,%3};"
                    : "+f"(acc[mf][nf][0]), "+f"(acc[mf][nf][1]),
                      "+f"(acc[mf][nf][2]), "+f"(acc[mf][nf][3])
                    : "r"(a[mf][0]), "r"(a[mf][1]), "r"(a[mf][2]), "r"(a[mf][3]),
                      "r"(b0), "r"(b1));
            }
        }
    }

    __half* out16 = (__half*)g_Pqh;
    #pragma unroll
    for (int mf = 0; mf < 2; mf++) {
        #pragma unroll
        for (int rs = 0; rs < 2; rs++) {
            int d = dbase + wm * 32 + mf * 16 + rs * 8 + (lane >> 2);
            if (d >= NUM_DST) continue;
            #pragma unroll
            for (int nf = 0; nf < 8; nf++) {
                int k0 = kbase + wn * 64 + nf * 8 + 2 * (lane & 3);
                #pragma unroll
                for (int q = 0; q < 2; q++) {
                    int k = k0 + q;
                    if (k < KDIM)
                        out16[((size_t)d * KDIM + k) * 2 + hh] =
                            __float2half_rn(acc[mf][nf][rs * 2 + q]);
                }
            }
        }
    }
}

// ---------------- kernel 2: per-edge warp (UNCHANGED R12/R13) ----------------
__global__ __launch_bounds__(256) void scoreU_kernel(
    const float* __restrict__ h,   const float* __restrict__ ef,
    const float* __restrict__ dt,  const int*   __restrict__ dst_idx,
    const float* __restrict__ time_w, const float* __restrict__ time_b)
{
    int e = (blockIdx.x * 256 + threadIdx.x) >> 5;
    if (e >= NUM_EDGES) return;
    int lane = threadIdx.x & 31;
    float td = dt[e];
    int d = dst_idx[e];
    const float* __restrict__ hrow  = h + (size_t)(NUM_DST + e) * DN;
    const float* __restrict__ efrow = ef + (size_t)e * DE;
    const int k2 = lane * 2;

    float2 v[NPC];
    #pragma unroll
    for (int it = 0; it < 5; it++) {
        int k = it * 64 + k2;
        float2 t;
        if (k < DN) {
            t = __ldcs((const float2*)(hrow + k));
        } else if (k < DN + DE) {
            t = __ldcs((const float2*)(efrow + (k - DN)));
        } else {
            int t0 = k - DN - DE;
            t.x = __cosf(td * time_w[t0]     + time_b[t0]);
            t.y = __cosf(td * time_w[t0 + 1] + time_b[t0 + 1]);
        }
        v[it] = t;
    }
    {
        int k = 5 * 64 + k2;
        float2 t = make_float2(0.f, 0.f);
        if (k < KDIM) {
            int t0 = k - DN - DE;
            t.x = __cosf(td * time_w[t0]     + time_b[t0]);
            t.y = __cosf(td * time_w[t0 + 1] + time_b[t0 + 1]);
        }
        v[5] = t;
    }

    const __half2* __restrict__ pq = g_Pqh + (size_t)d * KDIM;
    float2 p[NPC][2];
    #pragma unroll
    for (int it = 0; it < 5; it++) {
        uint2 raw = __ldg((const uint2*)(pq + it * 64 + k2));
        p[it][0] = __half22float2(*(__half2*)&raw.x);
        p[it][1] = __half22float2(*(__half2*)&raw.y);
    }
    if (5 * 64 + k2 < KDIM) {
        uint2 raw = __ldg((const uint2*)(pq + 5 * 64 + k2));
        p[5][0] = __half22float2(*(__half2*)&raw.x);
        p[5][1] = __half22float2(*(__half2*)&raw.y);
    } else {
        p[5][0] = make_float2(0.f, 0.f);
        p[5][1] = make_float2(0.f, 0.f);
    }

    float a0 = 0.f, a1 = 0.f;
    #pragma unroll
    for (int it = 0; it < NPC; it++) {
        a0 = fmaf(v[it].x, p[it][0].x, a0);
        a1 = fmaf(v[it].x, p[it][0].y, a1);
        a0 = fmaf(v[it].y, p[it][1].x, a0);
        a1 = fmaf(v[it].y, p[it][1].y, a1);
    }
    #pragma unroll
    for (int off = 16; off > 0; off >>= 1) {
        a0 += __shfl_xor_sync(0xffffffffu, a0, off);
        a1 += __shfl_xor_sync(0xffffffffu, a1, off);
    }
    float2 qbk = *(const float2*)(g_qbk + d * 2);
    float s0 = a0 + g_absum[0] + qbk.x;
    float s1 = a1 + g_absum[1] + qbk.y;
    s0 = s0 > 0.f ? s0 : 0.2f * s0;
    s1 = s1 > 0.f ? s1 : 0.2f * s1;
    float e0 = __expf(fminf(s0, 80.f));
    float e1 = __expf(fminf(s1, 80.f));
    if (lane == 0) {
        asm volatile("red.global.add.v2.f32 [%0], {%1,%2};"
                     :: "l"(g_z + d * 2), "f"(e0), "f"(e1) : "memory");
    }
    float2* __restrict__ Urow = g_U + (size_t)d * KDIM;
    #pragma unroll
    for (int it = 0; it < 5; it++) {
        int k = it * 64 + k2;
        float x0 = v[it].x * e0;
        float y0 = v[it].x * e1;
        float x1 = v[it].y * e0;
        float y1 = v[it].y * e1;
        asm volatile("red.global.add.v4.f32 [%0], {%1,%2,%3,%4};"
                     :: "l"(Urow + k), "f"(x0), "f"(y0), "f"(x1), "f"(y1)
                     : "memory");
    }
    if (5 * 64 + k2 < KDIM) {
        float x0 = v[5].x * e0;
        float y0 = v[5].x * e1;
        float x1 = v[5].y * e0;
        float y1 = v[5].y * e1;
        asm volatile("red.global.add.v4.f32 [%0], {%1,%2,%3,%4};"
                     :: "l"(Urow + 5 * 64 + k2), "f"(x0), "f"(y0), "f"(x1), "f"(y1)
                     : "memory");
    }
}

// ---------------- kernel 3: tail GEMMs via tf32 MMA + LN ---------------------
// One block = 128 dsts. Phase 1: agg = (U*rz) @ wv' (K=744 interleaved-head),
// +bv (z>0) -> sAgg. Phase 2: rst = relu([sAgg|h] @ wout + bout) -> sAgg.
// Then warp-per-row LayerNorm, float4 stores.
__global__ __launch_bounds__(256) void outmma_kernel(
    const float* __restrict__ h,    const float* __restrict__ wv,
    const float* __restrict__ bv,   const float* __restrict__ wout,
    const float* __restrict__ bout, const float* __restrict__ ln_g,
    const float* __restrict__ ln_b, float* __restrict__ out)
{
    extern __shared__ char sm_[];
    float (*sAgg)[132] = (float(*)[132])sm_;
    float (*As)[68]    = (float(*)[68])(sm_ + SM_AGG);
    float (*Bs)[136]   = (float(*)[136])(sm_ + SM_AGG + SM_AS);
    float (*sRZ)[2]    = (float(*)[2])(sm_ + SM_AGG + SM_AS + SM_BS);

    const int dbase = blockIdx.x * 128;
    const int tid  = threadIdx.x;
    const int lane = tid & 31;
    const int wid  = tid >> 5;
    const int wm   = wid & 3;
    const int wn   = wid >> 2;

    // reciprocal z (0 encodes empty dst)
    if (tid < 256) {
        int r = tid >> 1, j = tid & 1;
        int d = dbase + r;
        float z = (d < NUM_DST) ? g_z[d * 2 + j] : 0.f;
        sRZ[r][j] = (z > 0.f) ? (1.f / z) : 0.f;
    }
    __syncthreads();

    float acc[2][8][4];
    #pragma unroll
    for (int mf = 0; mf < 2; mf++)
        #pragma unroll
        for (int nf = 0; nf < 8; nf++)
            #pragma unroll
            for (int r = 0; r < 4; r++) acc[mf][nf][r] = 0.f;

    // ---- phase 1: 12 chunks of 64 over K'=744 ----
    const float* Uflat = (const float*)g_U;
    #pragma unroll 1
    for (int kc = 0; kc < 12; kc++) {
        for (int i = tid; i < 128 * 64; i += 256) {
            int r = i >> 6, c = i & 63;
            int kp = kc * 64 + c;
            int d = dbase + r;
            float vv = 0.f;
            if (d < NUM_DST && kp < KP1)
                vv = Uflat[(size_t)d * KP1 + kp] * sRZ[r][kp & 1];
            As[r][c] = __uint_as_float(to_tf32(vv));
        }
        for (int i = tid; i < 64 * 128; i += 256) {
            int n = i & 127, c = i >> 7;
            int kp = kc * 64 + c;
            float vv = 0.f;
            if (kp < KP1 && (n >> 6) == (kp & 1))
                vv = wv[(kp >> 1) * DOUT + n];
            Bs[c][n] = __uint_as_float(to_tf32(vv));
        }
        __syncthreads();
        #pragma unroll
        for (int ks = 0; ks < 8; ks++) {
            int acol = (lane & 3) + ks * 8;
            uint32_t a[2][4];
            #pragma unroll
            for (int mf = 0; mf < 2; mf++) {
                int rb = wm * 32 + mf * 16 + (lane >> 2);
                a[mf][0] = __float_as_uint(As[rb][acol]);
                a[mf][1] = __float_as_uint(As[rb + 8][acol]);
                a[mf][2] = __float_as_uint(As[rb][acol + 4]);
                a[mf][3] = __float_as_uint(As[rb + 8][acol + 4]);
            }
            int brow = (lane & 3) + ks * 8;
            #pragma unroll
            for (int nf = 0; nf < 8; nf++) {
                int bn = wn * 64 + nf * 8 + (lane >> 2);
                uint32_t b0 = __float_as_uint(Bs[brow][bn]);
                uint32_t b1 = __float_as_uint(Bs[brow + 4][bn]);
                #pragma unroll
                for (int mf = 0; mf < 2; mf++) {
                    asm volatile(
                        "mma.sync.aligned.m16n8k8.row.col.f32.tf32.tf32.f32 "
                        "{%0,%1,%2,%3}, {%4,%5,%6,%7}, {%8,%9}, {%0,%1,%2,%3};"
                        : "+f"(acc[mf][nf][0]), "+f"(acc[mf][nf][1]),
                          "+f"(acc[mf][nf][2]), "+f"(acc[mf][nf][3])
                        : "r"(a[mf][0]), "r"(a[mf][1]), "r"(a[mf][2]), "r"(a[mf][3]),
                          "r"(b0), "r"(b1));
                }
            }
        }
        __syncthreads();
    }
    // epilogue 1: sAgg = (z>0) ? acc + bv : 0
    #pragma unroll
    for (int mf = 0; mf < 2; mf++)
        #pragma unroll
        for (int rs = 0; rs < 2; rs++) {
            int row = wm * 32 + mf * 16 + rs * 8 + (lane >> 2);
            #pragma unroll
            for (int nf = 0; nf < 8; nf++)
                #pragma unroll
                for (int q = 0; q < 2; q++) {
                    int col = wn * 64 + nf * 8 + 2 * (lane & 3) + q;
                    float rz = sRZ[row][col >> 6];
                    sAgg[row][col] = (rz > 0.f)
                        ? (acc[mf][nf][rs * 2 + q] + __ldg(bv + col)) : 0.f;
                }
        }
    __syncthreads();

    // ---- phase 2: 4 chunks of 64 over K=228 (padded 256) ----
    #pragma unroll
    for (int mf = 0; mf < 2; mf++)
        #pragma unroll
        for (int nf = 0; nf < 8; nf++)
            #pragma unroll
            for (int r = 0; r < 4; r++) acc[mf][nf][r] = 0.f;

    #pragma unroll 1
    for (int kc = 0; kc < 4; kc++) {
        for (int i = tid; i < 128 * 64; i += 256) {
            int r = i >> 6, c = i & 63;
            int k = kc * 64 + c;
            float vv = 0.f;
            if (k < DOUT) {
                vv = sAgg[r][k];
            } else if (k < KO) {
                int d = dbase + r;
                vv = (d < NUM_DST) ? h[(size_t)d * DN + (k - DOUT)] : 0.f;
            }
            As[r][c] = __uint_as_float(to_tf32(vv));
        }
        for (int i = tid; i < 64 * 128; i += 256) {
            int n = i & 127, c = i >> 7;
            int k = kc * 64 + c;
            float vv = (k < KO) ? wout[k * DOUT + n] : 0.f;
            Bs[c][n] = __uint_as_float(to_tf32(vv));
        }
        __syncthreads();
        #pragma unroll
        for (int ks = 0; ks < 8; ks++) {
            int acol = (lane & 3) + ks * 8;
            uint32_t a[2][4];
            #pragma unroll
            for (int mf = 0; mf < 2; mf++) {
                int rb = wm * 32 + mf * 16 + (lane >> 2);
                a[mf][0] = __float_as_uint(As[rb][acol]);
                a[mf][1] = __float_as_uint(As[rb + 8][acol]);
                a[mf][2] = __float_as_uint(As[rb][acol + 4]);
                a[mf][3] = __float_as_uint(As[rb + 8][acol + 4]);
            }
            int brow = (lane & 3) + ks * 8;
            #pragma unroll
            for (int nf = 0; nf < 8; nf++) {
                int bn = wn * 64 + nf * 8 + (lane >> 2);
                uint32_t b0 = __float_as_uint(Bs[brow][bn]);
                uint32_t b1 = __float_as_uint(Bs[brow + 4][bn]);
                #pragma unroll
                for (int mf = 0; mf < 2; mf++) {
                    asm volatile(
                        "mma.sync.aligned.m16n8k8.row.col.f32.tf32.tf32.f32 "
                        "{%0,%1,%2,%3}, {%4,%5,%6,%7}, {%8,%9}, {%0,%1,%2,%3};"
                        : "+f"(acc[mf][nf][0]), "+f"(acc[mf][nf][1]),
                          "+f"(acc[mf][nf][2]), "+f"(acc[mf][nf][3])
                        : "r"(a[mf][0]), "r"(a[mf][1]), "r"(a[mf][2]), "r"(a[mf][3]),
                          "r"(b0), "r"(b1));
                }
            }
        }
        __syncthreads();
    }
    // epilogue 2: rst = relu(acc + bout) -> sAgg (safe: all MMA reads done)
    #pragma unroll
    for (int mf = 0; mf < 2; mf++)
        #pragma unroll
        for (int rs = 0; rs < 2; rs++) {
            int row = wm * 32 + mf * 16 + rs * 8 + (lane >> 2);
            #pragma unroll
            for (int nf = 0; nf < 8; nf++)
                #pragma unroll
                for (int q = 0; q < 2; q++) {
                    int col = wn * 64 + nf * 8 + 2 * (lane & 3) + q;
                    sAgg[row][col] =
                        fmaxf(acc[mf][nf][rs * 2 + q] + __ldg(bout + col), 0.f);
                }
        }
    __syncthreads();

    // ---- LayerNorm: warp wid handles rows wid*16 .. wid*16+15 ----
    float4 lg = *(const float4*)(ln_g + lane * 4);
    float4 lb = *(const float4*)(ln_b + lane * 4);
    for (int r0 = 0; r0 < 16; r0++) {
        int r = wid * 16 + r0;
        int d = dbase + r;
        float4 x = *(float4*)&sAgg[r][lane * 4];
        float s1 = x.x + x.y + x.z + x.w;
        float s2 = x.x * x.x + x.y * x.y + x.z * x.z + x.w * x.w;
        #pragma unroll
        for (int off = 16; off > 0; off >>= 1) {
            s1 += __shfl_xor_sync(0xffffffffu, s1, off);
            s2 += __shfl_xor_sync(0xffffffffu, s2, off);
        }
        float mu  = s1 * (1.f / DOUT);
        float var = s2 * (1.f / DOUT) - mu * mu;
        float rstd = rsqrtf(var + 1e-5f);
        if (d < NUM_DST) {
            float4 o;
            o.x = (x.x - mu) * rstd * lg.x + lb.x;
            o.y = (x.y - mu) * rstd * lg.y + lb.y;
            o.z = (x.z - mu) * rstd * lg.z + lb.z;
            o.w = (x.w - mu) * rstd * lg.w + lb.w;
            *(float4*)(out + (size_t)d * DOUT + lane * 4) = o;
        }
    }
}

// ---------------- launch -----------------------------------------------------
extern "C" void kernel_launch(void* const* d_in, const int* in_sizes, int n_in,
                              void* d_out, int out_size)
{
    int off = (n_in >= 18 && in_sizes[4] == 1) ? 1 : 0;
    const float* h        = (const float*)d_in[0];
    const float* ef       = (const float*)d_in[1];
    const float* dt       = (const float*)d_in[2];
    const int*   dst_idx  = (const int*)  d_in[3];
    const float* time_w   = (const float*)d_in[4 + off];
    const float* time_b   = (const float*)d_in[5 + off];
    const float* wq       = (const float*)d_in[6 + off];
    const float* bq       = (const float*)d_in[7 + off];
    const float* wk       = (const float*)d_in[8 + off];
    const float* bk       = (const float*)d_in[9 + off];
    const float* wv       = (const float*)d_in[10 + off];
    const float* bv       = (const float*)d_in[11 + off];
    const float* att_bias = (const float*)d_in[12 + off];
    const float* wout     = (const float*)d_in[13 + off];
    const float* bout     = (const float*)d_in[14 + off];
    const float* ln_g     = (const float*)d_in[15 + off];
    const float* ln_b     = (const float*)d_in[16 + off];
    float* out = (float*)d_out;

    cudaFuncSetAttribute(outmma_kernel,
                         cudaFuncAttributeMaxDynamicSharedMemorySize, OUT_SMEM);

    init_kernel<<<(U_FLOAT4 + 255) / 256, 256>>>(time_b, wq, bq, att_bias);
    qnode_kernel<<<NUM_DST / 8, 128>>>(h, wq, bk);
    pqmma_kernel<<<dim3((NUM_DST + 127) / 128, (KDIM + 127) / 128, 2), 256>>>(wk);
    scoreU_kernel<<<NUM_EDGES / 8, 256>>>(h, ef, dt, dst_idx, time_w, time_b);
    outmma_kernel<<<(NUM_DST + 127) / 128, 256, OUT_SMEM>>>(
        h, wv, bv, wout, bout, ln_g, ln_b, out);
}